// round 2
// baseline (speedup 1.0000x reference)
#include <cuda_runtime.h>
#include <cuda_bf16.h>

// Problem constants
#define LL 4096
#define HH 64
#define WW 64
#define DM 96
#define DI 192
#define DS 16
#define DTR 6
#define KK 4
#define CPROJ 38   // DT_RANK + 2*D_STATE

// ---------------- scratch (device globals; no allocation allowed) ----------------
__device__ float  g_xz[LL * 2 * DI];          // [l][384]  (x_ | z)
__device__ float  g_xc[LL * DI];              // [l][192]  conv+silu output
__device__ float2 g_du[KK * DI * LL];         // [k][d][l] = (delta, u)
__device__ float2 g_bc[KK * LL * DS];         // [k][l][n] = (B, C)
__device__ float  g_outy[KK * DI * LL];       // [k][d][l]
__device__ float  g_yg[LL * DI];              // [l][d]  normalized*gated

// ---------------- generic tiled GEMM: C(MxN) = A(MxKc) * B(NxKc)^T ----------------
template<int BM, int BN, int BK, int TM, int TN>
__global__ void gemm_abt(const float* __restrict__ A, const float* __restrict__ B,
                         float* __restrict__ C, int M, int N, int Kc) {
    __shared__ float As[BK][BM + 1];
    __shared__ float Bs[BK][BN + 1];
    int tid = threadIdx.x;                    // 256 threads
    int block_row = blockIdx.y * BM;
    int block_col = blockIdx.x * BN;
    int tr = (tid / (BN / TN)) * TM;
    int tc = (tid % (BN / TN)) * TN;
    float acc[TM][TN];
#pragma unroll
    for (int i = 0; i < TM; i++)
#pragma unroll
        for (int j = 0; j < TN; j++) acc[i][j] = 0.f;

    for (int k0 = 0; k0 < Kc; k0 += BK) {
        for (int i = tid; i < BM * BK; i += 256) {
            int r = i / BK, c = i % BK;
            int gr = block_row + r, gc = k0 + c;
            As[c][r] = (gr < M && gc < Kc) ? A[gr * Kc + gc] : 0.f;
        }
        for (int i = tid; i < BN * BK; i += 256) {
            int r = i / BK, c = i % BK;
            int gr = block_col + r, gc = k0 + c;
            Bs[c][r] = (gr < N && gc < Kc) ? B[gr * Kc + gc] : 0.f;
        }
        __syncthreads();
#pragma unroll
        for (int kk = 0; kk < BK; kk++) {
            float a[TM], b[TN];
#pragma unroll
            for (int i = 0; i < TM; i++) a[i] = As[kk][tr + i];
#pragma unroll
            for (int j = 0; j < TN; j++) b[j] = Bs[kk][tc + j];
#pragma unroll
            for (int i = 0; i < TM; i++)
#pragma unroll
                for (int j = 0; j < TN; j++) acc[i][j] = fmaf(a[i], b[j], acc[i][j]);
        }
        __syncthreads();
    }
#pragma unroll
    for (int i = 0; i < TM; i++) {
        int gr = block_row + tr + i;
        if (gr >= M) continue;
#pragma unroll
        for (int j = 0; j < TN; j++) {
            int gc = block_col + tc + j;
            if (gc < N) C[gr * N + gc] = acc[i][j];
        }
    }
}

// ---------------- depthwise 3x3 conv (SAME) + bias + SiLU ----------------
__global__ void conv_silu_kernel(const float* __restrict__ xz,
                                 const float* __restrict__ conv_w,
                                 const float* __restrict__ conv_b,
                                 float* __restrict__ xc) {
    int idx = blockIdx.x * 256 + threadIdx.x;
    if (idx >= LL * DI) return;
    int d = idx % DI, l = idx / DI;
    int i = l / WW, j = l % WW;
    float s = conv_b[d];
#pragma unroll
    for (int a = 0; a < 3; a++) {
        int ii = i + a - 1;
        if (ii < 0 || ii >= HH) continue;
#pragma unroll
        for (int bb = 0; bb < 3; bb++) {
            int jj = j + bb - 1;
            if (jj < 0 || jj >= WW) continue;
            s = fmaf(xz[(ii * WW + jj) * (2 * DI) + d], conv_w[(a * 3 + bb) * DI + d], s);
        }
    }
    xc[idx] = s / (1.f + __expf(-s));   // SiLU
}

// ---------------- x_dbl projection + delta (softplus) + pack scan inputs ----------------
// Block: 256 threads, handles one k and a tile of BL=32 scan positions.
__global__ void xdbl_kernel(const float* __restrict__ xc,
                            const float* __restrict__ x_proj_w,  // [K][38][192]
                            const float* __restrict__ dt_w,      // [K][192][6]
                            const float* __restrict__ dt_b,      // [K][192]
                            float2* __restrict__ du,             // [K][192][L]
                            float2* __restrict__ bc)             // [K][L][16]
{
    const int BL = 32;
    int k = blockIdx.y;
    int l0 = blockIdx.x * BL;
    int tid = threadIdx.x;
    __shared__ float u_s[BL][DI + 1];    // [li][c]
    __shared__ float xd_s[CPROJ][BL + 1];

    // load u tile: xs[k][c][l0+li] via index mapping into xc
    for (int e = tid; e < BL * DI; e += 256) {
        int li = e / DI, c = e % DI;
        int l = l0 + li;
        int lp = (k & 2) ? (LL - 1 - l) : l;                       // flip for k=2,3
        int sp = (k & 1) ? ((lp % WW) * WW + (lp / WW)) : lp;      // col-major for k=1,3
        u_s[li][c] = xc[sp * DI + c];
    }
    __syncthreads();

    const float* Wk = x_proj_w + k * CPROJ * DI;
    for (int e = tid; e < CPROJ * BL; e += 256) {
        int row = e / BL, li = e % BL;
        float s = 0.f;
#pragma unroll 8
        for (int c = 0; c < DI; c++) s = fmaf(Wk[row * DI + c], u_s[li][c], s);
        xd_s[row][li] = s;
    }
    __syncthreads();

    // delta = softplus(dts @ dt_w^T + dt_b), pack (delta, u)
    for (int e = tid; e < DI * BL; e += 256) {
        int d = e / BL, li = e % BL;
        float acc = dt_b[k * DI + d];
#pragma unroll
        for (int r = 0; r < DTR; r++) acc = fmaf(dt_w[(k * DI + d) * DTR + r], xd_s[r][li], acc);
        float delta = (acc > 20.f) ? acc : log1pf(expf(acc));
        du[(k * DI + d) * LL + l0 + li] = make_float2(delta, u_s[li][d]);
    }
    // pack (B, C)
    for (int e = tid; e < DS * BL; e += 256) {
        int li = e / DS, n = e % DS;
        bc[((size_t)k * LL + l0 + li) * DS + n] =
            make_float2(xd_s[DTR + n][li], xd_s[DTR + DS + n][li]);
    }
}

// ---------------- selective scan: one half-warp per (k,d), lane = state index ----------------
__global__ void scan_kernel(const float2* __restrict__ du,
                            const float2* __restrict__ bc,
                            const float* __restrict__ A_logs,  // [768][16]
                            const float* __restrict__ Ds,      // [768]
                            float* __restrict__ outy)          // [K][192][L]
{
    int s = blockIdx.x * 8 + (threadIdx.x >> 4);   // scan id 0..767
    int n = threadIdx.x & 15;
    int k = s / DI;
    float An = -__expf(A_logs[s * DS + n]);
    float Dv = Ds[s];
    const float2* dup = du + (size_t)s * LL;
    const float2* bcp = bc + (size_t)k * LL * DS;
    float* op = outy + (size_t)s * LL;

    float h = 0.f;
    float ybuf = 0.f;
    for (int l0 = 0; l0 < LL; l0 += 16) {
#pragma unroll
        for (int i = 0; i < 16; i++) {
            int l = l0 + i;
            float2 dv = dup[l];            // broadcast across 16 lanes
            float2 b  = bcp[l * DS + n];   // lane-indexed, 128B per half-warp
            float dA = __expf(dv.x * An);
            h = fmaf(dA, h, dv.x * dv.y * b.x);
            float y = h * b.y;
            y += __shfl_xor_sync(0xffffffffu, y, 1);
            y += __shfl_xor_sync(0xffffffffu, y, 2);
            y += __shfl_xor_sync(0xffffffffu, y, 4);
            y += __shfl_xor_sync(0xffffffffu, y, 8);
            if (n == i) ybuf = fmaf(Dv, dv.y, y);
        }
        op[l0 + n] = ybuf;   // coalesced 64B per half-warp
    }
}

// ---------------- sum over k + LayerNorm + SiLU(z) gate ----------------
__global__ void ln_gate_kernel(const float* __restrict__ outy,
                               const float* __restrict__ xz,
                               const float* __restrict__ ln_g,
                               const float* __restrict__ ln_b,
                               float* __restrict__ yg) {
    int l = blockIdx.x;
    int d = threadIdx.x;   // 192 threads
    float y = 0.f;
#pragma unroll
    for (int k = 0; k < KK; k++) y += outy[((size_t)k * DI + d) * LL + l];

    float s1 = y, s2 = y * y;
#pragma unroll
    for (int off = 16; off; off >>= 1) {
        s1 += __shfl_xor_sync(0xffffffffu, s1, off);
        s2 += __shfl_xor_sync(0xffffffffu, s2, off);
    }
    __shared__ float ws1[6], ws2[6];
    int w = d >> 5;
    if ((d & 31) == 0) { ws1[w] = s1; ws2[w] = s2; }
    __syncthreads();
    float t1 = 0.f, t2 = 0.f;
#pragma unroll
    for (int i = 0; i < 6; i++) { t1 += ws1[i]; t2 += ws2[i]; }
    float mu = t1 * (1.f / DI);
    float var = t2 * (1.f / DI) - mu * mu;
    float inv = rsqrtf(var + 1e-5f);
    float yn = fmaf((y - mu) * inv, ln_g[d], ln_b[d]);
    float z = xz[l * (2 * DI) + DI + d];
    yg[l * DI + d] = yn * (z / (1.f + __expf(-z)));
}

// ---------------- launch ----------------
extern "C" void kernel_launch(void* const* d_in, const int* in_sizes, int n_in,
                              void* d_out, int out_size) {
    const float* x        = (const float*)d_in[0];
    const float* in_proj  = (const float*)d_in[1];
    const float* conv_w   = (const float*)d_in[2];
    const float* conv_b   = (const float*)d_in[3];
    const float* x_proj_w = (const float*)d_in[4];
    const float* dt_w     = (const float*)d_in[5];
    const float* dt_b     = (const float*)d_in[6];
    const float* A_logs   = (const float*)d_in[7];
    const float* Ds       = (const float*)d_in[8];
    const float* ln_g     = (const float*)d_in[9];
    const float* ln_b     = (const float*)d_in[10];
    const float* out_w    = (const float*)d_in[11];
    float* out = (float*)d_out;

    float*  xz  = nullptr; cudaGetSymbolAddress((void**)&xz,  g_xz);
    float*  xc  = nullptr; cudaGetSymbolAddress((void**)&xc,  g_xc);
    float2* du  = nullptr; cudaGetSymbolAddress((void**)&du,  g_du);
    float2* bcp = nullptr; cudaGetSymbolAddress((void**)&bcp, g_bc);
    float*  oy  = nullptr; cudaGetSymbolAddress((void**)&oy,  g_outy);
    float*  yg  = nullptr; cudaGetSymbolAddress((void**)&yg,  g_yg);

    // 1) in_proj: xz(4096x384) = x(4096x96) @ in_proj_w(384x96)^T
    gemm_abt<64, 64, 16, 4, 4><<<dim3(6, 64), 256>>>(x, in_proj, xz, LL, 2 * DI, DM);
    // 2) depthwise conv + SiLU
    conv_silu_kernel<<<(LL * DI + 255) / 256, 256>>>(xz, conv_w, conv_b, xc);
    // 3) x_dbl projection + delta + pack scan inputs
    xdbl_kernel<<<dim3(LL / 32, KK), 256>>>(xc, x_proj_w, dt_w, dt_b, du, bcp);
    // 4) selective scan (768 half-warp scans)
    scan_kernel<<<96, 128>>>(du, bcp, A_logs, Ds, oy);
    // 5) sum over k + LN + gate
    ln_gate_kernel<<<LL, DI>>>(oy, xz, ln_g, ln_b, yg);
    // 6) out_proj: out(4096x96) = yg(4096x192) @ out_w(96x192)^T
    gemm_abt<64, 64, 16, 4, 4><<<dim3(2, 64), 256>>>(yg, out_w, out, LL, DM, DI);
}

// round 5
// speedup vs baseline: 2.6324x; 2.6324x over previous
#include <cuda_runtime.h>
#include <cuda_bf16.h>

// Problem constants
#define LL 4096
#define HH 64
#define WW 64
#define DM 96
#define DI 192
#define DS 16
#define DTR 6
#define KK 4
#define CPROJ 38   // DT_RANK + 2*D_STATE
#define NSCAN (KK * DI)   // 768
#define NC 64             // chunks per scan
#define CL (LL / NC)      // 64 positions per chunk

// ---------------- scratch (device globals; no allocation allowed) ----------------
__device__ float  g_xz[LL * 2 * DI];          // [l][384]  (x_ | z)
__device__ float  g_xc[LL * DI];              // [l][192]  conv+silu output
__device__ float2 g_du[NSCAN * LL];           // [s][l] = (delta, u)
__device__ float2 g_bc[KK * LL * DS];         // [k][l][n] = (B, C)
__device__ float  g_outy[NSCAN * LL];         // [s][l]
__device__ float  g_yg[LL * DI];              // [l][d]  normalized*gated
__device__ float  g_carryA[NSCAN * NC * DS];  // chunk dA product
__device__ float  g_carryB[NSCAN * NC * DS];  // chunk local final h
__device__ float  g_hin[NSCAN * NC * DS];     // incoming state per chunk

// ---------------- generic tiled GEMM: C(MxN) = A(MxKc) * B(NxKc)^T ----------------
template<int BM, int BN, int BK, int TM, int TN>
__global__ void gemm_abt(const float* __restrict__ A, const float* __restrict__ B,
                         float* __restrict__ C, int M, int N, int Kc) {
    __shared__ float As[BK][BM + 1];
    __shared__ float Bs[BK][BN + 1];
    int tid = threadIdx.x;                    // 256 threads
    int block_row = blockIdx.y * BM;
    int block_col = blockIdx.x * BN;
    int tr = (tid / (BN / TN)) * TM;
    int tc = (tid % (BN / TN)) * TN;
    float acc[TM][TN];
#pragma unroll
    for (int i = 0; i < TM; i++)
#pragma unroll
        for (int j = 0; j < TN; j++) acc[i][j] = 0.f;

    for (int k0 = 0; k0 < Kc; k0 += BK) {
        for (int i = tid; i < BM * BK; i += 256) {
            int r = i / BK, c = i % BK;
            int gr = block_row + r, gc = k0 + c;
            As[c][r] = (gr < M && gc < Kc) ? A[gr * Kc + gc] : 0.f;
        }
        for (int i = tid; i < BN * BK; i += 256) {
            int r = i / BK, c = i % BK;
            int gr = block_col + r, gc = k0 + c;
            Bs[c][r] = (gr < N && gc < Kc) ? B[gr * Kc + gc] : 0.f;
        }
        __syncthreads();
#pragma unroll
        for (int kk = 0; kk < BK; kk++) {
            float a[TM], b[TN];
#pragma unroll
            for (int i = 0; i < TM; i++) a[i] = As[kk][tr + i];
#pragma unroll
            for (int j = 0; j < TN; j++) b[j] = Bs[kk][tc + j];
#pragma unroll
            for (int i = 0; i < TM; i++)
#pragma unroll
                for (int j = 0; j < TN; j++) acc[i][j] = fmaf(a[i], b[j], acc[i][j]);
        }
        __syncthreads();
    }
#pragma unroll
    for (int i = 0; i < TM; i++) {
        int gr = block_row + tr + i;
        if (gr >= M) continue;
#pragma unroll
        for (int j = 0; j < TN; j++) {
            int gc = block_col + tc + j;
            if (gc < N) C[gr * N + gc] = acc[i][j];
        }
    }
}

// ---------------- depthwise 3x3 conv (SAME) + bias + SiLU ----------------
__global__ void conv_silu_kernel(const float* __restrict__ xz,
                                 const float* __restrict__ conv_w,
                                 const float* __restrict__ conv_b,
                                 float* __restrict__ xc) {
    int idx = blockIdx.x * 256 + threadIdx.x;
    if (idx >= LL * DI) return;
    int d = idx % DI, l = idx / DI;
    int i = l / WW, j = l % WW;
    float s = conv_b[d];
#pragma unroll
    for (int a = 0; a < 3; a++) {
        int ii = i + a - 1;
        if (ii < 0 || ii >= HH) continue;
#pragma unroll
        for (int bb = 0; bb < 3; bb++) {
            int jj = j + bb - 1;
            if (jj < 0 || jj >= WW) continue;
            s = fmaf(xz[(ii * WW + jj) * (2 * DI) + d], conv_w[(a * 3 + bb) * DI + d], s);
        }
    }
    xc[idx] = s / (1.f + __expf(-s));   // SiLU
}

// ---------------- x_dbl projection + delta (softplus) + pack scan inputs ----------------
__global__ void xdbl_kernel(const float* __restrict__ xc,
                            const float* __restrict__ x_proj_w,  // [K][38][192]
                            const float* __restrict__ dt_w,      // [K][192][6]
                            const float* __restrict__ dt_b,      // [K][192]
                            float2* __restrict__ du,             // [K*192][L]
                            float2* __restrict__ bc)             // [K][L][16]
{
    const int BL = 32;
    int k = blockIdx.y;
    int l0 = blockIdx.x * BL;
    int tid = threadIdx.x;
    __shared__ float u_s[BL][DI + 1];    // [li][c]
    __shared__ float xd_s[CPROJ][BL + 1];

    for (int e = tid; e < BL * DI; e += 256) {
        int li = e / DI, c = e % DI;
        int l = l0 + li;
        int lp = (k & 2) ? (LL - 1 - l) : l;                       // flip for k=2,3
        int sp = (k & 1) ? ((lp % WW) * WW + (lp / WW)) : lp;      // col-major for k=1,3
        u_s[li][c] = xc[sp * DI + c];
    }
    __syncthreads();

    const float* Wk = x_proj_w + k * CPROJ * DI;
    for (int e = tid; e < CPROJ * BL; e += 256) {
        int row = e / BL, li = e % BL;
        float s = 0.f;
#pragma unroll 8
        for (int c = 0; c < DI; c++) s = fmaf(Wk[row * DI + c], u_s[li][c], s);
        xd_s[row][li] = s;
    }
    __syncthreads();

    for (int e = tid; e < DI * BL; e += 256) {
        int d = e / BL, li = e % BL;
        float acc = dt_b[k * DI + d];
#pragma unroll
        for (int r = 0; r < DTR; r++) acc = fmaf(dt_w[(k * DI + d) * DTR + r], xd_s[r][li], acc);
        float delta = (acc > 20.f) ? acc : log1pf(expf(acc));
        du[(k * DI + d) * LL + l0 + li] = make_float2(delta, u_s[li][d]);
    }
    for (int e = tid; e < DS * BL; e += 256) {
        int li = e / DS, n = e % DS;
        bc[((size_t)k * LL + l0 + li) * DS + n] =
            make_float2(xd_s[DTR + n][li], xd_s[DTR + DS + n][li]);
    }
}

// ---------------- scan pass 1: per-chunk transfer (P = prod dA, h = local final) ----------------
__global__ void scan_pass1(const float2* __restrict__ du,
                           const float2* __restrict__ bc,
                           const float* __restrict__ A_logs,
                           float* __restrict__ carryA,
                           float* __restrict__ carryB)
{
    int hw = blockIdx.x * 8 + (threadIdx.x >> 4);   // 0 .. NSCAN*NC-1
    int n = threadIdx.x & 15;
    int c = hw / NSCAN;        // chunk index (block shares chunk, consecutive scans)
    int s = hw % NSCAN;
    int k = s / DI;
    float An = -__expf(A_logs[s * DS + n]);
    const float2* dup = du + (size_t)s * LL + c * CL;
    const float2* bcp = bc + ((size_t)k * LL + c * CL) * DS;

    float P = 1.f, h = 0.f;
#pragma unroll 8
    for (int i = 0; i < CL; i++) {
        float2 dv = dup[i];
        float2 b  = bcp[i * DS + n];
        float dA = __expf(dv.x * An);
        P *= dA;
        h = fmaf(dA, h, dv.x * dv.y * b.x);
    }
    carryA[((size_t)s * NC + c) * DS + n] = P;
    carryB[((size_t)s * NC + c) * DS + n] = h;
}

// ---------------- scan combine: fold chunk transfers sequentially ----------------
__global__ void scan_combine(const float* __restrict__ carryA,
                             const float* __restrict__ carryB,
                             float* __restrict__ hin)
{
    int s = blockIdx.x * 8 + (threadIdx.x >> 4);    // 0..767
    int n = threadIdx.x & 15;
    float h = 0.f;
    size_t base = (size_t)s * NC * DS + n;
    for (int c = 0; c < NC; c++) {
        hin[base + (size_t)c * DS] = h;
        h = fmaf(carryA[base + (size_t)c * DS], h, carryB[base + (size_t)c * DS]);
    }
}

// ---------------- scan pass 2: recompute chunk with seeded state, emit y ----------------
__global__ void scan_pass2(const float2* __restrict__ du,
                           const float2* __restrict__ bc,
                           const float* __restrict__ A_logs,
                           const float* __restrict__ Ds,
                           const float* __restrict__ hin,
                           float* __restrict__ outy)
{
    int hw = blockIdx.x * 8 + (threadIdx.x >> 4);
    int n = threadIdx.x & 15;
    int c = hw / NSCAN;
    int s = hw % NSCAN;
    int k = s / DI;
    float An = -__expf(A_logs[s * DS + n]);
    float Dv = Ds[s];
    const float2* dup = du + (size_t)s * LL + c * CL;
    const float2* bcp = bc + ((size_t)k * LL + c * CL) * DS;
    float* op = outy + (size_t)s * LL + c * CL;

    float h = hin[((size_t)s * NC + c) * DS + n];
    float ybuf = 0.f;
    for (int l0 = 0; l0 < CL; l0 += 16) {
#pragma unroll
        for (int i = 0; i < 16; i++) {
            int l = l0 + i;
            float2 dv = dup[l];
            float2 b  = bcp[l * DS + n];
            float dA = __expf(dv.x * An);
            h = fmaf(dA, h, dv.x * dv.y * b.x);
            float y = h * b.y;
            y += __shfl_xor_sync(0xffffffffu, y, 1);
            y += __shfl_xor_sync(0xffffffffu, y, 2);
            y += __shfl_xor_sync(0xffffffffu, y, 4);
            y += __shfl_xor_sync(0xffffffffu, y, 8);
            if (n == i) ybuf = fmaf(Dv, dv.y, y);
        }
        op[l0 + n] = ybuf;   // coalesced 64B per half-warp
    }
}

// ---------------- sum over k + LayerNorm + SiLU(z) gate (coalesced) ----------------
__global__ void ln_gate_kernel(const float* __restrict__ outy,
                               const float* __restrict__ xz,
                               const float* __restrict__ ln_g,
                               const float* __restrict__ ln_b,
                               float* __restrict__ yg) {
    const int TL = 32;
    int l0 = blockIdx.x * TL;
    int tid = threadIdx.x;   // 256
    __shared__ float ys[TL][DI + 1];

    // load + k-sum, coalesced over l
    for (int e = tid; e < TL * DI; e += 256) {
        int li = e & 31, d = e >> 5;
        float v = 0.f;
#pragma unroll
        for (int k = 0; k < KK; k++)
            v += outy[((size_t)(k * DI + d)) * LL + l0 + li];
        ys[li][d] = v;
    }
    __syncthreads();

    int w = tid >> 5, lane = tid & 31;
#pragma unroll
    for (int q = 0; q < 4; q++) {
        int li = w * 4 + q;
        int l = l0 + li;
        float v[6];
        float s1 = 0.f, s2 = 0.f;
#pragma unroll
        for (int j = 0; j < 6; j++) {
            v[j] = ys[li][lane + 32 * j];
            s1 += v[j];
            s2 += v[j] * v[j];
        }
#pragma unroll
        for (int off = 16; off; off >>= 1) {
            s1 += __shfl_xor_sync(0xffffffffu, s1, off);
            s2 += __shfl_xor_sync(0xffffffffu, s2, off);
        }
        float mu = s1 * (1.f / DI);
        float var = s2 * (1.f / DI) - mu * mu;
        float inv = rsqrtf(var + 1e-5f);
#pragma unroll
        for (int j = 0; j < 6; j++) {
            int d = lane + 32 * j;
            float yn = fmaf((v[j] - mu) * inv, ln_g[d], ln_b[d]);
            float z = xz[l * (2 * DI) + DI + d];
            yg[l * DI + d] = yn * (z / (1.f + __expf(-z)));
        }
    }
}

// ---------------- launch ----------------
extern "C" void kernel_launch(void* const* d_in, const int* in_sizes, int n_in,
                              void* d_out, int out_size) {
    const float* x        = (const float*)d_in[0];
    const float* in_proj  = (const float*)d_in[1];
    const float* conv_w   = (const float*)d_in[2];
    const float* conv_b   = (const float*)d_in[3];
    const float* x_proj_w = (const float*)d_in[4];
    const float* dt_w     = (const float*)d_in[5];
    const float* dt_b     = (const float*)d_in[6];
    const float* A_logs   = (const float*)d_in[7];
    const float* Ds       = (const float*)d_in[8];
    const float* ln_g     = (const float*)d_in[9];
    const float* ln_b     = (const float*)d_in[10];
    const float* out_w    = (const float*)d_in[11];
    float* out = (float*)d_out;

    float*  xz  = nullptr; cudaGetSymbolAddress((void**)&xz,  g_xz);
    float*  xc  = nullptr; cudaGetSymbolAddress((void**)&xc,  g_xc);
    float2* du  = nullptr; cudaGetSymbolAddress((void**)&du,  g_du);
    float2* bcp = nullptr; cudaGetSymbolAddress((void**)&bcp, g_bc);
    float*  oy  = nullptr; cudaGetSymbolAddress((void**)&oy,  g_outy);
    float*  yg  = nullptr; cudaGetSymbolAddress((void**)&yg,  g_yg);
    float*  cA  = nullptr; cudaGetSymbolAddress((void**)&cA,  g_carryA);
    float*  cB  = nullptr; cudaGetSymbolAddress((void**)&cB,  g_carryB);
    float*  hin = nullptr; cudaGetSymbolAddress((void**)&hin, g_hin);

    // 1) in_proj: xz(4096x384) = x(4096x96) @ in_proj_w(384x96)^T
    gemm_abt<64, 64, 16, 4, 4><<<dim3(6, 64), 256>>>(x, in_proj, xz, LL, 2 * DI, DM);
    // 2) depthwise conv + SiLU
    conv_silu_kernel<<<(LL * DI + 255) / 256, 256>>>(xz, conv_w, conv_b, xc);
    // 3) x_dbl projection + delta + pack scan inputs
    xdbl_kernel<<<dim3(LL / 32, KK), 256>>>(xc, x_proj_w, dt_w, dt_b, du, bcp);
    // 4) chunked selective scan
    scan_pass1<<<NSCAN * NC / 8, 128>>>(du, bcp, A_logs, cA, cB);
    scan_combine<<<NSCAN / 8, 128>>>(cA, cB, hin);
    scan_pass2<<<NSCAN * NC / 8, 128>>>(du, bcp, A_logs, Ds, hin, oy);
    // 5) sum over k + LN + gate
    ln_gate_kernel<<<LL / 32, 256>>>(oy, xz, ln_g, ln_b, yg);
    // 6) out_proj: out(4096x96) = yg(4096x192) @ out_w(96x192)^T
    gemm_abt<64, 64, 16, 4, 4><<<dim3(2, 64), 256>>>(yg, out_w, out, LL, DM, DI);
}